// round 2
// baseline (speedup 1.0000x reference)
#include <cuda_runtime.h>
#include <math.h>

// Problem constants
#define BATCH 4
#define CH    64
#define HH    128
#define WW    128
#define HW    16384            // 128*128
#define CHW   1048576          // 64*16384 = 2^20
#define NTOT  4194304          // 4*64*128*128

static __device__ __constant__ float kMODSCALE = 1.0f / 24.0f; // 1/sqrt(64*3*3)

// Scratch: 9 activation-sized buffers (CUR, TMP, S1, S3, S5, E1..E4)
__device__ float g_buf[9][NTOT];
__device__ float g_mx[BATCH * CH];
__device__ float g_av[BATCH * CH];
__device__ float g_cf[BATCH * CH];

// ---------------------------------------------------------------------------
// 3x3 conv, pad=1.  MOD: per-in-channel modulation (cond), weight*1/24,
// bias index (b*64+oc)/4.  ACT: 0 none, 1 relu, 2 leaky-relu(0.01).
// RES: add residual tensor elementwise.
// Block: 256 thr = 64 oc x 4 quadrants.  Tile: 16(w) x 8(h).  Thread: 8x4 px.
// ---------------------------------------------------------------------------
template<int MOD, int ACT, int RES>
__global__ void __launch_bounds__(256, 2) conv3_kernel(
    const float* __restrict__ x, const float* __restrict__ w,
    const float* __restrict__ bias, const float* __restrict__ cond,
    const float* __restrict__ res, float* __restrict__ out)
{
    __shared__ float s_in[4][10][18];     // [icl][y][x] with halo
    __shared__ float s_w[4][64 * 9];      // [icl][oc*9+k]

    const int tid = threadIdx.x;
    const int oc = tid & 63;
    const int q  = tid >> 6;
    const int qx = (q & 1) * 8;
    const int qy = (q >> 1) * 4;
    const int gx0 = blockIdx.x * 16;
    const int gy0 = blockIdx.y * 8;
    const int b   = blockIdx.z;

    float acc[4][8];
#pragma unroll
    for (int r = 0; r < 4; r++)
#pragma unroll
        for (int c = 0; c < 8; c++) acc[r][c] = 0.f;

    const float* xb = x + (size_t)b * CHW;

    for (int ic0 = 0; ic0 < 64; ic0 += 4) {
        __syncthreads();
        // ---- stage input tile (4 ic x 10 x 18), modulated + zero-padded ----
        for (int e = tid; e < 720; e += 256) {
            int icl = e / 180, rem = e % 180;
            int yy = rem / 18, xx = rem % 18;
            int gy = gy0 + yy - 1, gx = gx0 + xx - 1;
            float v = 0.f;
            if ((unsigned)gy < 128u && (unsigned)gx < 128u) {
                v = xb[(ic0 + icl) * HW + gy * 128 + gx];
                if (MOD) v *= cond[b * 64 + ic0 + icl];
            }
            s_in[icl][yy][xx] = v;
        }
        // ---- stage weights (4 ic x 64 oc x 9) ----
        for (int e = tid; e < 2304; e += 256) {
            int ocw = e / 36, r2 = e % 36;
            int icl = r2 / 9, k = r2 % 9;
            float wv = w[(ocw * 64 + ic0 + icl) * 9 + k];
            if (MOD) wv *= kMODSCALE;
            s_w[icl][ocw * 9 + k] = wv;
        }
        __syncthreads();

#pragma unroll
        for (int icl = 0; icl < 4; icl++) {
            float wv[9];
#pragma unroll
            for (int k = 0; k < 9; k++) wv[k] = s_w[icl][oc * 9 + k];
            float rows[6][10];
#pragma unroll
            for (int r = 0; r < 6; r++)
#pragma unroll
                for (int j = 0; j < 10; j++) rows[r][j] = s_in[icl][qy + r][qx + j];
#pragma unroll
            for (int rr = 0; rr < 4; rr++)
#pragma unroll
                for (int c = 0; c < 8; c++) {
                    float s = acc[rr][c];
                    s += rows[rr + 0][c] * wv[0] + rows[rr + 0][c + 1] * wv[1] + rows[rr + 0][c + 2] * wv[2];
                    s += rows[rr + 1][c] * wv[3] + rows[rr + 1][c + 1] * wv[4] + rows[rr + 1][c + 2] * wv[5];
                    s += rows[rr + 2][c] * wv[6] + rows[rr + 2][c + 1] * wv[7] + rows[rr + 2][c + 2] * wv[8];
                    acc[rr][c] = s;
                }
        }
    }

    const float bv = MOD ? bias[(b * 64 + oc) >> 2] : bias[oc];
    float* ob = out + (size_t)(b * 64 + oc) * HW;
    const float* rb = RES ? (res + (size_t)(b * 64 + oc) * HW) : nullptr;

#pragma unroll
    for (int rr = 0; rr < 4; rr++) {
        int base = (gy0 + qy + rr) * 128 + gx0 + qx;
        float t[8];
#pragma unroll
        for (int c = 0; c < 8; c++) {
            float v = acc[rr][c] + bv;
            if (ACT == 1) v = fmaxf(v, 0.f);
            if (ACT == 2) v = v > 0.f ? v : 0.01f * v;
            t[c] = v;
        }
        if (RES) {
            float4 q0 = *(const float4*)(rb + base);
            float4 q1 = *(const float4*)(rb + base + 4);
            t[0] += q0.x; t[1] += q0.y; t[2] += q0.z; t[3] += q0.w;
            t[4] += q1.x; t[5] += q1.y; t[6] += q1.z; t[7] += q1.w;
        }
        *(float4*)(ob + base)     = make_float4(t[0], t[1], t[2], t[3]);
        *(float4*)(ob + base + 4) = make_float4(t[4], t[5], t[6], t[7]);
    }
}

// ---------------------------------------------------------------------------
// 5x5 conv, pad=2.  Same tiling as conv3.  ACT: 0 none, 2 lrelu.
// ---------------------------------------------------------------------------
template<int ACT>
__global__ void __launch_bounds__(256, 2) conv5_kernel(
    const float* __restrict__ x, const float* __restrict__ w,
    const float* __restrict__ bias, float* __restrict__ out)
{
    __shared__ float s_in[2][12][20];
    __shared__ float s_w[2][64 * 25];

    const int tid = threadIdx.x;
    const int oc = tid & 63;
    const int q  = tid >> 6;
    const int qx = (q & 1) * 8;
    const int qy = (q >> 1) * 4;
    const int gx0 = blockIdx.x * 16;
    const int gy0 = blockIdx.y * 8;
    const int b   = blockIdx.z;

    float acc[4][8];
#pragma unroll
    for (int r = 0; r < 4; r++)
#pragma unroll
        for (int c = 0; c < 8; c++) acc[r][c] = 0.f;

    const float* xb = x + (size_t)b * CHW;

    for (int ic0 = 0; ic0 < 64; ic0 += 2) {
        __syncthreads();
        for (int e = tid; e < 480; e += 256) {
            int icl = e / 240, rem = e % 240;
            int yy = rem / 20, xx = rem % 20;
            int gy = gy0 + yy - 2, gx = gx0 + xx - 2;
            float v = 0.f;
            if ((unsigned)gy < 128u && (unsigned)gx < 128u)
                v = xb[(ic0 + icl) * HW + gy * 128 + gx];
            s_in[icl][yy][xx] = v;
        }
        for (int e = tid; e < 3200; e += 256) {
            int ocw = e / 50, r2 = e % 50;
            int icl = r2 / 25, k = r2 % 25;
            s_w[icl][ocw * 25 + k] = w[(ocw * 64 + ic0 + icl) * 25 + k];
        }
        __syncthreads();

#pragma unroll
        for (int icl = 0; icl < 2; icl++) {
            float wv[25];
#pragma unroll
            for (int k = 0; k < 25; k++) wv[k] = s_w[icl][oc * 25 + k];
#pragma unroll
            for (int rr = 0; rr < 4; rr++) {
#pragma unroll
                for (int kh = 0; kh < 5; kh++) {
                    float rb_[12];
#pragma unroll
                    for (int j = 0; j < 12; j++) rb_[j] = s_in[icl][qy + rr + kh][qx + j];
#pragma unroll
                    for (int c = 0; c < 8; c++) {
                        float s = acc[rr][c];
                        s += rb_[c + 0] * wv[kh * 5 + 0];
                        s += rb_[c + 1] * wv[kh * 5 + 1];
                        s += rb_[c + 2] * wv[kh * 5 + 2];
                        s += rb_[c + 3] * wv[kh * 5 + 3];
                        s += rb_[c + 4] * wv[kh * 5 + 4];
                        acc[rr][c] = s;
                    }
                }
            }
        }
    }

    const float bv = bias[oc];
    float* ob = out + (size_t)(b * 64 + oc) * HW;
#pragma unroll
    for (int rr = 0; rr < 4; rr++) {
        int base = (gy0 + qy + rr) * 128 + gx0 + qx;
        float t[8];
#pragma unroll
        for (int c = 0; c < 8; c++) {
            float v = acc[rr][c] + bv;
            if (ACT == 2) v = v > 0.f ? v : 0.01f * v;
            t[c] = v;
        }
        *(float4*)(ob + base)     = make_float4(t[0], t[1], t[2], t[3]);
        *(float4*)(ob + base + 4) = make_float4(t[4], t[5], t[6], t[7]);
    }
}

// ---------------------------------------------------------------------------
// 1x1 conv (GEMM 64x64 per pixel).  Block: 64 px x 64 oc (4 groups of 16).
// ---------------------------------------------------------------------------
template<int ACT>
__global__ void __launch_bounds__(256) conv1_kernel(
    const float* __restrict__ x, const float* __restrict__ w,
    const float* __restrict__ bias, float* __restrict__ out)
{
    __shared__ float xs[64][64];                  // [ic][px]
    __shared__ __align__(16) float ws[64][68];    // [ic][oc] padded

    const int tid = threadIdx.x;
    const int b  = blockIdx.y;
    const int p0 = blockIdx.x * 64;

    for (int e = tid; e < 4096; e += 256) {
        int ic = e >> 6, px = e & 63;
        xs[ic][px] = x[(size_t)b * CHW + ic * HW + p0 + px];
    }
    for (int e = tid; e < 4096; e += 256) {
        int ocw = e >> 6, ic = e & 63;
        ws[ic][ocw] = w[ocw * 64 + ic];
    }
    __syncthreads();

    const int px = tid & 63;
    const int oc0 = (tid >> 6) * 16;
    float acc[16];
#pragma unroll
    for (int o = 0; o < 16; o++) acc[o] = 0.f;

#pragma unroll 4
    for (int ic = 0; ic < 64; ic++) {
        float xv = xs[ic][px];
        const float4* wr = (const float4*)&ws[ic][oc0];
        float4 w0 = wr[0], w1 = wr[1], w2 = wr[2], w3 = wr[3];
        acc[0]  += xv * w0.x;  acc[1]  += xv * w0.y;  acc[2]  += xv * w0.z;  acc[3]  += xv * w0.w;
        acc[4]  += xv * w1.x;  acc[5]  += xv * w1.y;  acc[6]  += xv * w1.z;  acc[7]  += xv * w1.w;
        acc[8]  += xv * w2.x;  acc[9]  += xv * w2.y;  acc[10] += xv * w2.z;  acc[11] += xv * w2.w;
        acc[12] += xv * w3.x;  acc[13] += xv * w3.y;  acc[14] += xv * w3.z;  acc[15] += xv * w3.w;
    }
#pragma unroll
    for (int o = 0; o < 16; o++) {
        float v = acc[o] + bias[oc0 + o];
        if (ACT == 2) v = v > 0.f ? v : 0.01f * v;
        out[(size_t)b * CHW + (oc0 + o) * HW + p0 + px] = v;
    }
}

// ---------------------------------------------------------------------------
// Global max + mean over HxW per (b,c).  One block per (b,c).
// ---------------------------------------------------------------------------
__global__ void pool_kernel(const float* __restrict__ x,
                            float* __restrict__ mx, float* __restrict__ av)
{
    const int bc = blockIdx.x;
    const float* p = x + (size_t)bc * HW;
    float m = -3.402823466e38f, s = 0.f;
    for (int i = threadIdx.x; i < HW; i += 256) {
        float v = p[i];
        m = fmaxf(m, v);
        s += v;
    }
#pragma unroll
    for (int o = 16; o; o >>= 1) {
        m = fmaxf(m, __shfl_xor_sync(0xFFFFFFFFu, m, o));
        s += __shfl_xor_sync(0xFFFFFFFFu, s, o);
    }
    __shared__ float sm_[8], ss_[8];
    int wid = threadIdx.x >> 5;
    if ((threadIdx.x & 31) == 0) { sm_[wid] = m; ss_[wid] = s; }
    __syncthreads();
    if (threadIdx.x == 0) {
        float mm = sm_[0], st = ss_[0];
        for (int i = 1; i < 8; i++) { mm = fmaxf(mm, sm_[i]); st += ss_[i]; }
        mx[bc] = mm;
        av[bc] = st * (1.0f / 16384.0f);
    }
}

// ---------------------------------------------------------------------------
// Channel attention + FC1 coefficient:
//   se(v) = relu(v @ cw1^T) @ cw2^T ; xll = sigmoid(se(mx)+se(av))
//   C = fw1*(fw0*xll + fb0) + fb1
// ---------------------------------------------------------------------------
__global__ void coef_kernel(const float* __restrict__ mx, const float* __restrict__ av,
                            const float* __restrict__ cw1, const float* __restrict__ cw2,
                            const float* __restrict__ fw, const float* __restrict__ fb,
                            float* __restrict__ coef)
{
    __shared__ float hm[16], ha[16];
    int t = threadIdx.x;
    if (t < 32) {
        int which = t >> 4;
        int t2 = t & 15;
        int b = t2 >> 2, j = t2 & 3;
        const float* v = which ? av : mx;
        float s = 0.f;
        for (int c = 0; c < 64; c++) s += v[b * 64 + c] * cw1[j * 64 + c];
        s = fmaxf(s, 0.f);
        if (which) ha[t2] = s; else hm[t2] = s;
    }
    __syncthreads();
    int b = t >> 6, c = t & 63;
    float se_m = 0.f, se_a = 0.f;
#pragma unroll
    for (int j = 0; j < 4; j++) {
        se_m += hm[b * 4 + j] * cw2[c * 4 + j];
        se_a += ha[b * 4 + j] * cw2[c * 4 + j];
    }
    float xll = 1.f / (1.f + expf(-(se_m + se_a)));
    coef[t] = fw[1] * (fw[0] * xll + fb[0]) + fb[1];
}

// out = coef[bc] * (s1 + s3 + s5)
__global__ void combine_kernel(const float* __restrict__ s1, const float* __restrict__ s3,
                               const float* __restrict__ s5, const float* __restrict__ coef,
                               float* __restrict__ out)
{
    int i = blockIdx.x * 256 + threadIdx.x;
    int fi = i * 4;
    float cf = coef[fi >> 14];
    float4 a = *(const float4*)(s1 + fi);
    float4 b = *(const float4*)(s3 + fi);
    float4 c = *(const float4*)(s5 + fi);
    float4 r;
    r.x = cf * (a.x + b.x + c.x);
    r.y = cf * (a.y + b.y + c.y);
    r.z = cf * (a.z + b.z + c.z);
    r.w = cf * (a.w + b.w + c.w);
    *(float4*)(out + fi) = r;
}

__global__ void add_kernel(float* __restrict__ a, const float* __restrict__ b)
{
    int fi = (blockIdx.x * 256 + threadIdx.x) * 4;
    float4 u = *(float4*)(a + fi);
    float4 v = *(const float4*)(b + fi);
    u.x += v.x; u.y += v.y; u.z += v.z; u.w += v.w;
    *(float4*)(a + fi) = u;
}

// a = a*map + a = a*(1+map), map broadcast over channels
__global__ void mapmul_kernel(float* __restrict__ a, const float* __restrict__ mp)
{
    int fi = (blockIdx.x * 256 + threadIdx.x) * 4;
    int b = fi >> 20;          // / (64*HW)
    int s = fi & (HW - 1);
    float4 m = *(const float4*)(mp + b * HW + s);
    float4 v = *(float4*)(a + fi);
    v.x *= (1.f + m.x); v.y *= (1.f + m.y); v.z *= (1.f + m.z); v.w *= (1.f + m.w);
    *(float4*)(a + fi) = v;
}

// ---------------------------------------------------------------------------
extern "C" void kernel_launch(void* const* d_in, const int* in_sizes, int n_in,
                              void* d_out, int out_size)
{
    (void)in_sizes; (void)n_in; (void)out_size;
    const float* x   = (const float*)d_in[0];
    const float* c1  = (const float*)d_in[1];   // [9,2,4,64]
    const float* c2  = (const float*)d_in[2];   // [1,2,4,64]
    const float* mp  = (const float*)d_in[3];   // [4,1,128,128]
    const float* rw  = (const float*)d_in[4];   // [9,2,64,64,3,3]
    const float* rb  = (const float*)d_in[5];   // [9,2,64]
    const float* w1  = (const float*)d_in[6];   // [5,2,64,64,1,1]
    const float* b1  = (const float*)d_in[7];
    const float* w3  = (const float*)d_in[8];   // [5,2,64,64,3,3]
    const float* b3  = (const float*)d_in[9];
    const float* w5  = (const float*)d_in[10];  // [5,2,64,64,5,5]
    const float* b5  = (const float*)d_in[11];
    const float* cw1 = (const float*)d_in[12];  // [5,4,64]
    const float* cw2 = (const float*)d_in[13];  // [5,64,4]
    const float* fw  = (const float*)d_in[14];  // [5,2]
    const float* fb  = (const float*)d_in[15];  // [5,2]
    float* OUT = (float*)d_out;

    float* base;
    cudaGetSymbolAddress((void**)&base, g_buf);
    float* CUR = base;
    float* TMP = base + (size_t)NTOT;
    float* S1  = base + 2 * (size_t)NTOT;
    float* S3  = base + 3 * (size_t)NTOT;
    float* S5  = base + 4 * (size_t)NTOT;
    float* E1  = base + 5 * (size_t)NTOT;
    float* E2  = base + 6 * (size_t)NTOT;
    float* E3  = base + 7 * (size_t)NTOT;
    float* E4  = base + 8 * (size_t)NTOT;
    float *MX, *AV, *CF;
    cudaGetSymbolAddress((void**)&MX, g_mx);
    cudaGetSymbolAddress((void**)&AV, g_av);
    cudaGetSymbolAddress((void**)&CF, g_cf);

    const dim3 G3(8, 16, 4);   // 16x8 tiles, batch
    const dim3 G1(256, 4);     // 64-px tiles, batch
    const int EG = NTOT / 4 / 256; // 4096

    // Resblock: out = modconv2(relu(modconv1(in))) + in   (in may equal out)
    auto resb = [&](const float* in, float* out, int i, const float* cond) {
        const float* wi = rw + (size_t)i * 2 * 64 * 64 * 9;
        const float* bi = rb + (size_t)i * 2 * 64;
        conv3_kernel<1, 1, 0><<<G3, 256>>>(in, wi, bi, cond, nullptr, TMP);
        conv3_kernel<1, 0, 1><<<G3, 256>>>(TMP, wi + 64 * 64 * 9, bi + 64, cond + 256, in, out);
    };

    // MFE (in-place on CUR)
    auto mfe = [&](int i) {
        pool_kernel<<<256, 256>>>(CUR, MX, AV);
        coef_kernel<<<1, 256>>>(MX, AV, cw1 + i * 256, cw2 + i * 256, fw + i * 2, fb + i * 2, CF);
        const float* w1i = w1 + (size_t)i * 2 * 64 * 64;
        const float* w3i = w3 + (size_t)i * 2 * 64 * 64 * 9;
        const float* w5i = w5 + (size_t)i * 2 * 64 * 64 * 25;
        conv1_kernel<2><<<G1, 256>>>(CUR, w1i, b1 + i * 128, TMP);
        conv1_kernel<0><<<G1, 256>>>(TMP, w1i + 64 * 64, b1 + i * 128 + 64, S1);
        conv3_kernel<0, 2, 0><<<G3, 256>>>(CUR, w3i, b3 + i * 128, nullptr, nullptr, TMP);
        conv3_kernel<0, 0, 0><<<G3, 256>>>(TMP, w3i + 64 * 64 * 9, b3 + i * 128 + 64, nullptr, nullptr, S3);
        conv5_kernel<2><<<G3, 256>>>(CUR, w5i, b5 + i * 128, TMP);
        conv5_kernel<0><<<G3, 256>>>(TMP, w5i + 64 * 64 * 25, b5 + i * 128 + 64, S5);
        combine_kernel<<<EG, 256>>>(S1, S3, S5, CF, CUR);
    };

    const size_t NB = (size_t)NTOT * sizeof(float);

    // --------- network ---------
    resb(x, CUR, 0, c1);                                    // e1 = R0(x)
    mfe(0);                                                 // e1 = M0(e1)
    resb(CUR, CUR, 0, c1);                                  // e1 = R0(e1)
    cudaMemcpyAsync(E1, CUR, NB, cudaMemcpyDeviceToDevice);

    for (int k = 0; k < 3; k++) resb(CUR, CUR, 1, c1 + 512);    // e2
    cudaMemcpyAsync(E2, CUR, NB, cudaMemcpyDeviceToDevice);

    resb(CUR, CUR, 2, c1 + 1024); mfe(1); resb(CUR, CUR, 2, c1 + 1024); // e3
    cudaMemcpyAsync(E3, CUR, NB, cudaMemcpyDeviceToDevice);

    for (int k = 0; k < 3; k++) resb(CUR, CUR, 3, c1 + 1536);   // e4
    cudaMemcpyAsync(E4, CUR, NB, cudaMemcpyDeviceToDevice);

    resb(CUR, CUR, 4, c2);                                  // e5 = R4
    mfe(2);                                                 // e5 = M2
    mapmul_kernel<<<EG, 256>>>(CUR, mp);                    // e5 = e5*map + e5
    resb(CUR, CUR, 4, c2);                                  // e5 = R4
    add_kernel<<<EG, 256>>>(CUR, E4);                       // e5 += e4

    for (int k = 0; k < 3; k++) resb(CUR, CUR, 5, c1 + 5 * 512); // d6

    add_kernel<<<EG, 256>>>(CUR, E3);                       // d7 = e3 + d6
    resb(CUR, CUR, 6, c1 + 6 * 512); mfe(3); resb(CUR, CUR, 6, c1 + 6 * 512);

    add_kernel<<<EG, 256>>>(CUR, E2);                       // d8 = e2 + d7
    for (int k = 0; k < 3; k++) resb(CUR, CUR, 7, c1 + 7 * 512);

    add_kernel<<<EG, 256>>>(CUR, E1);                       // d9 = e1 + d8
    resb(CUR, CUR, 8, c1 + 8 * 512);
    mfe(4);
    // final resblock writes straight to d_out
    {
        const float* wi = rw + (size_t)8 * 2 * 64 * 64 * 9;
        const float* bi = rb + (size_t)8 * 2 * 64;
        const float* cond = c1 + 8 * 512;
        conv3_kernel<1, 1, 0><<<G3, 256>>>(CUR, wi, bi, cond, nullptr, TMP);
        conv3_kernel<1, 0, 1><<<G3, 256>>>(TMP, wi + 64 * 64 * 9, bi + 64, cond + 256, CUR, OUT);
    }
}

// round 5
// speedup vs baseline: 3.2123x; 3.2123x over previous
#include <cuda_runtime.h>
#include <cuda_bf16.h>
#include <cstdint>
#include <math.h>

#define HW    16384
#define CHW   1048576
#define NTOT  4194304

__device__ float g_buf[9][NTOT];
__device__ float g_mx[256];
__device__ float g_av[256];
__device__ float g_cf[256];
__device__ __align__(16) char g_w3pack[28 * 9 * 16384];
__device__ __align__(16) char g_w5pack[10 * 25 * 16384];

// byte-in-tile swizzle: row*128 + b  ->  row*128 + (b ^ ((row&7)<<4))
#define SWZ128(o) ((o) ^ (((o) >> 3) & 0x70))

__device__ __forceinline__ uint32_t smem_u32(const void* p) {
    uint32_t a;
    asm("{ .reg .u64 t; cvta.to.shared.u64 t, %1; cvt.u32.u64 %0, t; }" : "=r"(a) : "l"(p));
    return a;
}
#define LDMX4(r, addr) \
    asm volatile("ldmatrix.sync.aligned.m8n8.x4.shared.b16 {%0,%1,%2,%3}, [%4];" \
        : "=r"((r)[0]), "=r"((r)[1]), "=r"((r)[2]), "=r"((r)[3]) : "r"(addr))
#define MMA16816(c, a, b) \
    asm volatile("mma.sync.aligned.m16n8k16.row.col.f32.bf16.bf16.f32 " \
        "{%0,%1,%2,%3}, {%4,%5,%6,%7}, {%8,%9}, {%0,%1,%2,%3};" \
        : "+f"((c)[0]), "+f"((c)[1]), "+f"((c)[2]), "+f"((c)[3]) \
        : "r"((a)[0]), "r"((a)[1]), "r"((a)[2]), "r"((a)[3]), "r"((b)[0]), "r"((b)[1]))
#define CPASYNC16(dst, src) \
    asm volatile("cp.async.ca.shared.global [%0], [%1], 16;" :: "r"(dst), "l"(src))
#define CPCOMMIT() asm volatile("cp.async.commit_group;")

// ---------------- weight prep: hi/lo bf16, swizzled tile image per tap ----------------
// per tap 16KB: [hi 8KB: 64 oc rows x 128B of ic][lo 8KB same]
__global__ void prep3_kernel(const float* __restrict__ rw, const float* __restrict__ w3,
                             char* __restrict__ dst)
{
    const int t = blockIdx.x, c = blockIdx.y;
    const float* w = (c < 18) ? (rw + (size_t)c * 36864) : (w3 + (size_t)(c - 18) * 36864);
    const float scale = (c < 18) ? (1.0f / 24.0f) : 1.0f;
    char* d = dst + ((size_t)c * 9 + t) * 16384;
    for (int e = threadIdx.x; e < 4096; e += 256) {
        int oc = e >> 6, ic = e & 63;
        float v = w[(oc * 64 + ic) * 9 + t] * scale;
        __nv_bfloat16 h = __float2bfloat16(v);
        __nv_bfloat16 l = __float2bfloat16(v - __bfloat162float(h));
        uint32_t off = SWZ128((uint32_t)(oc * 128 + ic * 2));
        *(unsigned short*)(d + off)        = __bfloat16_as_ushort(h);
        *(unsigned short*)(d + 8192 + off) = __bfloat16_as_ushort(l);
    }
}
__global__ void prep5_kernel(const float* __restrict__ w5, char* __restrict__ dst)
{
    const int t = blockIdx.x, c = blockIdx.y;
    const float* w = w5 + (size_t)c * 102400;
    char* d = dst + ((size_t)c * 25 + t) * 16384;
    for (int e = threadIdx.x; e < 4096; e += 256) {
        int oc = e >> 6, ic = e & 63;
        float v = w[(oc * 64 + ic) * 25 + t];
        __nv_bfloat16 h = __float2bfloat16(v);
        __nv_bfloat16 l = __float2bfloat16(v - __bfloat162float(h));
        uint32_t off = SWZ128((uint32_t)(oc * 128 + ic * 2));
        *(unsigned short*)(d + off)        = __bfloat16_as_ushort(h);
        *(unsigned short*)(d + 8192 + off) = __bfloat16_as_ushort(l);
    }
}

// ---------------------------------------------------------------------------
// bf16 HMMA conv (KDIM 3 or 5), pad=KDIM/2.
// CTA 256 thr = 8 warps: warp = wn*4+wm; wm in 0..3 (M: 32 px), wn in 0..1 (N: 32 oc).
// Tile: 16(w) x 8(h) = 128 px; pixel m = y*16+x.
// A: SMEM halo tile, rows = pixel (iy*IW+ix), 128B of 64 ic bf16, swizzled; hi+lo.
// B: per-tap 16KB (hi/lo) prefetched via cp.async, double buffered.
// Split: acc += Ahi*Bhi + Ahi*Blo + Alo*Bhi  (fp32 accum).
// ---------------------------------------------------------------------------
template<int KDIM, int MOD, int ACT, int RES>
__global__ void __launch_bounds__(256) convMMA_kernel(
    const float* __restrict__ x, const char* __restrict__ wpack,
    const float* __restrict__ bias, const float* __restrict__ cond,
    const float* __restrict__ res, float* __restrict__ out)
{
    constexpr int TAPS = KDIM * KDIM;
    constexpr int HALO = KDIM / 2;
    constexpr int IW = 16 + 2 * HALO;
    constexpr int IH = 8 + 2 * HALO;
    constexpr int NR = IH * IW;

    extern __shared__ __align__(16) char sm[];
    char* actH = sm;
    char* actL = sm + NR * 128;
    char* wts  = sm + 2 * NR * 128;   // 2 x 16KB

    const int tid = threadIdx.x, lane = tid & 31, warp = tid >> 5;
    const int wm = warp & 3, wn = warp >> 2;
    const int gx0 = blockIdx.x * 16, gy0 = blockIdx.y * 8, b = blockIdx.z;
    const int cb = b * 64;
    const float* xb = x + (size_t)b * CHW;

    // ---- stage activation halo tile as bf16 hi/lo (swizzled rows) ----
    for (int e = tid; e < 32 * NR; e += 256) {
        int j = e / NR, p = e - j * NR;          // j = ic pair, p = pixel row
        int iy = p / IW, ix = p - iy * IW;
        int gy = gy0 + iy - HALO, gx = gx0 + ix - HALO;
        float v0 = 0.f, v1 = 0.f;
        if ((unsigned)gy < 128u && (unsigned)gx < 128u) {
            const float* q = xb + (size_t)(2 * j) * HW + gy * 128 + gx;
            v0 = q[0]; v1 = q[HW];
            if (MOD) { v0 *= cond[cb + 2 * j]; v1 *= cond[cb + 2 * j + 1]; }
        }
        __nv_bfloat16 h0 = __float2bfloat16(v0), h1 = __float2bfloat16(v1);
        __nv_bfloat16 l0 = __float2bfloat16(v0 - __bfloat162float(h0));
        __nv_bfloat16 l1 = __float2bfloat16(v1 - __bfloat162float(h1));
        uint32_t off = (uint32_t)p * 128 + ((4u * j) ^ ((uint32_t)(p & 7) << 4));
        *(uint32_t*)(actH + off) = ((uint32_t)__bfloat16_as_ushort(h1) << 16) | __bfloat16_as_ushort(h0);
        *(uint32_t*)(actL + off) = ((uint32_t)__bfloat16_as_ushort(l1) << 16) | __bfloat16_as_ushort(l0);
    }

    const uint32_t actHa = smem_u32(actH);
    const uint32_t actLa = smem_u32(actL);
    const uint32_t wtsA  = smem_u32(wts);

    // weight prefetch (16KB per tap, 4 x 16B per thread)
    auto prefetch = [&](int tap, int buf) {
        const char* src = wpack + (size_t)tap * 16384;
        uint32_t dst = wtsA + ((uint32_t)buf << 14);
#pragma unroll
        for (int i = 0; i < 4; i++)
            CPASYNC16(dst + (tid + i * 256) * 16, src + (tid + i * 256) * 16);
        CPCOMMIT();
    };
    prefetch(0, 0);

    float c[2][4][4];
#pragma unroll
    for (int mi = 0; mi < 2; mi++)
#pragma unroll
        for (int ni = 0; ni < 4; ni++)
#pragma unroll
            for (int k = 0; k < 4; k++) c[mi][ni][k] = 0.f;

    // lane decode: A ldmatrix.x4 (mats: m0-7/k0, m8-15/k0, m0-7/k1, m8-15/k1)
    const int asub = lane >> 3;
    const int arow = ((asub & 1) << 3) + (lane & 7);   // m-local 0..15 (== x)
    const int ack  = asub >> 1;                        // k 16B-chunk offset 0/1
    // B ldmatrix.x4 (mats: oc0-7/ck0, oc0-7/ck1, oc8-15/ck0, oc8-15/ck1)
    const int bmat = lane >> 3;
    const int bocl = ((bmat >> 1) << 3) + (lane & 7);
    const int bck  = bmat & 1;

    for (int t = 0; t < TAPS; ++t) {
        if (t + 1 < TAPS) { prefetch(t + 1, (t + 1) & 1); asm volatile("cp.async.wait_group 1;"); }
        else              { asm volatile("cp.async.wait_group 0;"); }
        __syncthreads();   // tap-t weights visible to all; acts visible (t==0)

        const int ky = t / KDIM, kx = t - ky * KDIM;
        const uint32_t wb = wtsA + ((uint32_t)(t & 1) << 14);

#pragma unroll
        for (int ks = 0; ks < 4; ++ks) {
            uint32_t AH[2][4], AL[2][4], BH[4][2], BL[4][2];
#pragma unroll
            for (int mi = 0; mi < 2; ++mi) {
                int rp = (wm * 2 + mi + ky) * IW + arow + kx;
                uint32_t off = (uint32_t)rp * 128 + ((uint32_t)((ks * 2 + ack) ^ (rp & 7)) << 4);
                LDMX4(AH[mi], actHa + off);
                LDMX4(AL[mi], actLa + off);
            }
#pragma unroll
            for (int gg = 0; gg < 2; ++gg) {
                int ocr = wn * 32 + gg * 16 + bocl;
                uint32_t off = (uint32_t)ocr * 128 + ((uint32_t)((ks * 2 + bck) ^ (ocr & 7)) << 4);
                uint32_t r[4];
                LDMX4(r, wb + off);
                BH[gg * 2][0] = r[0]; BH[gg * 2][1] = r[1];
                BH[gg * 2 + 1][0] = r[2]; BH[gg * 2 + 1][1] = r[3];
                LDMX4(r, wb + 8192 + off);
                BL[gg * 2][0] = r[0]; BL[gg * 2][1] = r[1];
                BL[gg * 2 + 1][0] = r[2]; BL[gg * 2 + 1][1] = r[3];
            }
#pragma unroll
            for (int mi = 0; mi < 2; ++mi)
#pragma unroll
                for (int ni = 0; ni < 4; ++ni) {
                    MMA16816(c[mi][ni], AH[mi], BH[ni]);
                    MMA16816(c[mi][ni], AH[mi], BL[ni]);
                    MMA16816(c[mi][ni], AL[mi], BH[ni]);
                }
        }
        __syncthreads();   // all warps done with buf (t&1) before it is refilled at t+2
    }

    // ---- epilogue ----
    const int r0 = lane >> 2, q2 = (lane & 3) * 2;
#pragma unroll
    for (int mi = 0; mi < 2; ++mi) {
        const int y = wm * 2 + mi;
#pragma unroll
        for (int half = 0; half < 2; ++half) {
            const int xcol = r0 + half * 8;
            const int sp = (gy0 + y) * 128 + gx0 + xcol;
#pragma unroll
            for (int ni = 0; ni < 4; ++ni) {
#pragma unroll
                for (int dq = 0; dq < 2; ++dq) {
                    const int n = wn * 32 + ni * 8 + q2 + dq;
                    float v = c[mi][ni][half * 2 + dq];
                    v += MOD ? __ldg(&bias[(cb + n) >> 2]) : __ldg(&bias[n]);
                    if (ACT == 1) v = fmaxf(v, 0.f);
                    if (ACT == 2) v = v > 0.f ? v : 0.01f * v;
                    if (RES) v += __ldg(&res[(size_t)(cb + n) * HW + sp]);
                    out[(size_t)(cb + n) * HW + sp] = v;
                }
            }
        }
    }
}

// ---------------- fp32 1x1 conv ----------------
template<int ACT>
__global__ void __launch_bounds__(256) conv1_kernel(
    const float* __restrict__ x, const float* __restrict__ w,
    const float* __restrict__ bias, float* __restrict__ out)
{
    __shared__ float xs[64][64];
    __shared__ __align__(16) float ws[64][68];
    const int tid = threadIdx.x;
    const int b  = blockIdx.y;
    const int p0 = blockIdx.x * 64;
    for (int e = tid; e < 4096; e += 256) {
        int ic = e >> 6, px = e & 63;
        xs[ic][px] = x[(size_t)b * CHW + ic * HW + p0 + px];
    }
    for (int e = tid; e < 4096; e += 256) {
        int ocw = e >> 6, ic = e & 63;
        ws[ic][ocw] = w[ocw * 64 + ic];
    }
    __syncthreads();
    const int px = tid & 63;
    const int oc0 = (tid >> 6) * 16;
    float acc[16];
#pragma unroll
    for (int o = 0; o < 16; o++) acc[o] = 0.f;
#pragma unroll 4
    for (int ic = 0; ic < 64; ic++) {
        float xv = xs[ic][px];
        const float4* wr = (const float4*)&ws[ic][oc0];
        float4 w0 = wr[0], w1 = wr[1], w2 = wr[2], w3 = wr[3];
        acc[0]+=xv*w0.x; acc[1]+=xv*w0.y; acc[2]+=xv*w0.z; acc[3]+=xv*w0.w;
        acc[4]+=xv*w1.x; acc[5]+=xv*w1.y; acc[6]+=xv*w1.z; acc[7]+=xv*w1.w;
        acc[8]+=xv*w2.x; acc[9]+=xv*w2.y; acc[10]+=xv*w2.z; acc[11]+=xv*w2.w;
        acc[12]+=xv*w3.x; acc[13]+=xv*w3.y; acc[14]+=xv*w3.z; acc[15]+=xv*w3.w;
    }
#pragma unroll
    for (int o = 0; o < 16; o++) {
        float v = acc[o] + bias[oc0 + o];
        if (ACT == 2) v = v > 0.f ? v : 0.01f * v;
        out[(size_t)b * CHW + (oc0 + o) * HW + p0 + px] = v;
    }
}

// ---------------- small kernels ----------------
__global__ void pool_kernel(const float* __restrict__ x, float* __restrict__ mx, float* __restrict__ av)
{
    const int bc = blockIdx.x;
    const float* p = x + (size_t)bc * HW;
    float m = -3.402823466e38f, s = 0.f;
    for (int i = threadIdx.x; i < HW; i += 256) { float v = p[i]; m = fmaxf(m, v); s += v; }
#pragma unroll
    for (int o = 16; o; o >>= 1) {
        m = fmaxf(m, __shfl_xor_sync(0xFFFFFFFFu, m, o));
        s += __shfl_xor_sync(0xFFFFFFFFu, s, o);
    }
    __shared__ float sm_[8], ss_[8];
    int wid = threadIdx.x >> 5;
    if ((threadIdx.x & 31) == 0) { sm_[wid] = m; ss_[wid] = s; }
    __syncthreads();
    if (threadIdx.x == 0) {
        float mm = sm_[0], st = ss_[0];
        for (int i = 1; i < 8; i++) { mm = fmaxf(mm, sm_[i]); st += ss_[i]; }
        mx[bc] = mm; av[bc] = st * (1.0f / 16384.0f);
    }
}
__global__ void coef_kernel(const float* __restrict__ mx, const float* __restrict__ av,
                            const float* __restrict__ cw1, const float* __restrict__ cw2,
                            const float* __restrict__ fw, const float* __restrict__ fb,
                            float* __restrict__ coef)
{
    __shared__ float hm[16], ha[16];
    int t = threadIdx.x;
    if (t < 32) {
        int which = t >> 4, t2 = t & 15, b = t2 >> 2, j = t2 & 3;
        const float* v = which ? av : mx;
        float s = 0.f;
        for (int c = 0; c < 64; c++) s += v[b * 64 + c] * cw1[j * 64 + c];
        s = fmaxf(s, 0.f);
        if (which) ha[t2] = s; else hm[t2] = s;
    }
    __syncthreads();
    int b = t >> 6, c = t & 63;
    float se_m = 0.f, se_a = 0.f;
#pragma unroll
    for (int j = 0; j < 4; j++) {
        se_m += hm[b * 4 + j] * cw2[c * 4 + j];
        se_a += ha[b * 4 + j] * cw2[c * 4 + j];
    }
    float xll = 1.f / (1.f + expf(-(se_m + se_a)));
    coef[t] = fw[1] * (fw[0] * xll + fb[0]) + fb[1];
}
__global__ void combine_kernel(const float* __restrict__ s1, const float* __restrict__ s3,
                               const float* __restrict__ s5, const float* __restrict__ coef,
                               float* __restrict__ out)
{
    int fi = (blockIdx.x * 256 + threadIdx.x) * 4;
    float cf = coef[fi >> 14];
    float4 a = *(const float4*)(s1 + fi);
    float4 b = *(const float4*)(s3 + fi);
    float4 c = *(const float4*)(s5 + fi);
    float4 r;
    r.x = cf * (a.x + b.x + c.x); r.y = cf * (a.y + b.y + c.y);
    r.z = cf * (a.z + b.z + c.z); r.w = cf * (a.w + b.w + c.w);
    *(float4*)(out + fi) = r;
}
__global__ void add_kernel(float* __restrict__ a, const float* __restrict__ b)
{
    int fi = (blockIdx.x * 256 + threadIdx.x) * 4;
    float4 u = *(float4*)(a + fi);
    float4 v = *(const float4*)(b + fi);
    u.x += v.x; u.y += v.y; u.z += v.z; u.w += v.w;
    *(float4*)(a + fi) = u;
}
__global__ void mapmul_kernel(float* __restrict__ a, const float* __restrict__ mp)
{
    int fi = (blockIdx.x * 256 + threadIdx.x) * 4;
    int b = fi >> 20, s = fi & (HW - 1);
    float4 m = *(const float4*)(mp + b * HW + s);
    float4 v = *(float4*)(a + fi);
    v.x *= (1.f + m.x); v.y *= (1.f + m.y); v.z *= (1.f + m.z); v.w *= (1.f + m.w);
    *(float4*)(a + fi) = v;
}

// ---------------- launch ----------------
template<int KDIM, int MOD, int ACT, int RES>
static void launch_conv(const float* x, const char* wp, const float* bias,
                        const float* cond, const float* res, float* out)
{
    constexpr int HALO = KDIM / 2;
    constexpr int NR = (8 + 2 * HALO) * (16 + 2 * HALO);
    constexpr int SMEMB = 2 * NR * 128 + 2 * 16384;
    cudaFuncSetAttribute(convMMA_kernel<KDIM, MOD, ACT, RES>,
                         cudaFuncAttributeMaxDynamicSharedMemorySize, SMEMB);
    convMMA_kernel<KDIM, MOD, ACT, RES><<<dim3(8, 16, 4), 256, SMEMB>>>(x, wp, bias, cond, res, out);
}

extern "C" void kernel_launch(void* const* d_in, const int* in_sizes, int n_in,
                              void* d_out, int out_size)
{
    (void)in_sizes; (void)n_in; (void)out_size;
    const float* x   = (const float*)d_in[0];
    const float* c1  = (const float*)d_in[1];
    const float* c2  = (const float*)d_in[2];
    const float* mp  = (const float*)d_in[3];
    const float* rw  = (const float*)d_in[4];
    const float* rb  = (const float*)d_in[5];
    const float* w1  = (const float*)d_in[6];
    const float* b1  = (const float*)d_in[7];
    const float* w3  = (const float*)d_in[8];
    const float* b3  = (const float*)d_in[9];
    const float* w5  = (const float*)d_in[10];
    const float* b5  = (const float*)d_in[11];
    const float* cw1 = (const float*)d_in[12];
    const float* cw2 = (const float*)d_in[13];
    const float* fw  = (const float*)d_in[14];
    const float* fb  = (const float*)d_in[15];
    float* OUT = (float*)d_out;

    float* base;  cudaGetSymbolAddress((void**)&base, g_buf);
    char* W3P;    cudaGetSymbolAddress((void**)&W3P, g_w3pack);
    char* W5P;    cudaGetSymbolAddress((void**)&W5P, g_w5pack);
    float *MX, *AV, *CF;
    cudaGetSymbolAddress((void**)&MX, g_mx);
    cudaGetSymbolAddress((void**)&AV, g_av);
    cudaGetSymbolAddress((void**)&CF, g_cf);

    float* CUR = base;
    float* TMP = base + (size_t)NTOT;
    float* S1  = base + 2 * (size_t)NTOT;
    float* S3  = base + 3 * (size_t)NTOT;
    float* S5  = base + 4 * (size_t)NTOT;
    float* E1  = base + 5 * (size_t)NTOT;
    float* E2  = base + 6 * (size_t)NTOT;
    float* E3  = base + 7 * (size_t)NTOT;
    float* E4  = base + 8 * (size_t)NTOT;

    prep3_kernel<<<dim3(9, 28), 256>>>(rw, w3, W3P);
    prep5_kernel<<<dim3(25, 10), 256>>>(w5, W5P);

    const dim3 G1(256, 4);
    const int EG = NTOT / 4 / 256;

    auto resb = [&](const float* in, float* out, int i, const float* cond) {
        const char* wp = W3P + (size_t)(i * 2) * 9 * 16384;
        const float* bi = rb + (size_t)i * 2 * 64;
        launch_conv<3, 1, 1, 0>(in, wp, bi, cond, nullptr, TMP);
        launch_conv<3, 1, 0, 1>(TMP, wp + 9 * 16384, bi + 64, cond + 256, in, out);
    };
    auto mfe = [&](int i) {
        pool_kernel<<<256, 256>>>(CUR, MX, AV);
        coef_kernel<<<1, 256>>>(MX, AV, cw1 + i * 256, cw2 + i * 256, fw + i * 2, fb + i * 2, CF);
        const float* w1i = w1 + (size_t)i * 2 * 64 * 64;
        const char* w3p = W3P + (size_t)(18 + i * 2) * 9 * 16384;
        const char* w5p = W5P + (size_t)(i * 2) * 25 * 16384;
        conv1_kernel<2><<<G1, 256>>>(CUR, w1i, b1 + i * 128, TMP);
        conv1_kernel<0><<<G1, 256>>>(TMP, w1i + 64 * 64, b1 + i * 128 + 64, S1);
        launch_conv<3, 0, 2, 0>(CUR, w3p, b3 + i * 128, nullptr, nullptr, TMP);
        launch_conv<3, 0, 0, 0>(TMP, w3p + 9 * 16384, b3 + i * 128 + 64, nullptr, nullptr, S3);
        launch_conv<5, 0, 2, 0>(CUR, w5p, b5 + i * 128, nullptr, nullptr, TMP);
        launch_conv<5, 0, 0, 0>(TMP, w5p + 25 * 16384, b5 + i * 128 + 64, nullptr, nullptr, S5);
        combine_kernel<<<EG, 256>>>(S1, S3, S5, CF, CUR);
    };

    const size_t NB = (size_t)NTOT * sizeof(float);

    resb(x, CUR, 0, c1); mfe(0); resb(CUR, CUR, 0, c1);
    cudaMemcpyAsync(E1, CUR, NB, cudaMemcpyDeviceToDevice);

    for (int k = 0; k < 3; k++) resb(CUR, CUR, 1, c1 + 512);
    cudaMemcpyAsync(E2, CUR, NB, cudaMemcpyDeviceToDevice);

    resb(CUR, CUR, 2, c1 + 1024); mfe(1); resb(CUR, CUR, 2, c1 + 1024);
    cudaMemcpyAsync(E3, CUR, NB, cudaMemcpyDeviceToDevice);

    for (int k = 0; k < 3; k++) resb(CUR, CUR, 3, c1 + 1536);
    cudaMemcpyAsync(E4, CUR, NB, cudaMemcpyDeviceToDevice);

    resb(CUR, CUR, 4, c2); mfe(2);
    mapmul_kernel<<<EG, 256>>>(CUR, mp);
    resb(CUR, CUR, 4, c2);
    add_kernel<<<EG, 256>>>(CUR, E4);

    for (int k = 0; k < 3; k++) resb(CUR, CUR, 5, c1 + 5 * 512);

    add_kernel<<<EG, 256>>>(CUR, E3);
    resb(CUR, CUR, 6, c1 + 6 * 512); mfe(3); resb(CUR, CUR, 6, c1 + 6 * 512);

    add_kernel<<<EG, 256>>>(CUR, E2);
    for (int k = 0; k < 3; k++) resb(CUR, CUR, 7, c1 + 7 * 512);

    add_kernel<<<EG, 256>>>(CUR, E1);
    resb(CUR, CUR, 8, c1 + 8 * 512);
    mfe(4);
    {
        const char* wp = W3P + (size_t)(8 * 2) * 9 * 16384;
        const float* bi = rb + (size_t)8 * 2 * 64;
        const float* cond = c1 + 8 * 512;
        launch_conv<3, 1, 1, 0>(CUR, wp, bi, cond, nullptr, TMP);
        launch_conv<3, 1, 0, 1>(TMP, wp + 9 * 16384, bi + 64, cond + 256, CUR, OUT);
    }
}

// round 6
// speedup vs baseline: 3.4287x; 1.0674x over previous
#include <cuda_runtime.h>
#include <cuda_bf16.h>
#include <cstdint>
#include <math.h>

#define HW    16384
#define CHW   1048576
#define NTOT  4194304

__device__ float g_buf[9][NTOT];
__device__ float g_mx[256];
__device__ float g_av[256];
__device__ float g_cf[256];
__device__ __align__(16) char g_w3pack[28 * 9 * 16384];
__device__ __align__(16) char g_w5pack[10 * 25 * 16384];

#define SWZ128(o) ((o) ^ (((o) >> 3) & 0x70))

__device__ __forceinline__ uint32_t smem_u32(const void* p) {
    uint32_t a;
    asm("{ .reg .u64 t; cvta.to.shared.u64 t, %1; cvt.u32.u64 %0, t; }" : "=r"(a) : "l"(p));
    return a;
}
#define LDMX4(r, addr) \
    asm volatile("ldmatrix.sync.aligned.m8n8.x4.shared.b16 {%0,%1,%2,%3}, [%4];" \
        : "=r"((r)[0]), "=r"((r)[1]), "=r"((r)[2]), "=r"((r)[3]) : "r"(addr))
#define MMA16816(c, a, b) \
    asm volatile("mma.sync.aligned.m16n8k16.row.col.f32.bf16.bf16.f32 " \
        "{%0,%1,%2,%3}, {%4,%5,%6,%7}, {%8,%9}, {%0,%1,%2,%3};" \
        : "+f"((c)[0]), "+f"((c)[1]), "+f"((c)[2]), "+f"((c)[3]) \
        : "r"((a)[0]), "r"((a)[1]), "r"((a)[2]), "r"((a)[3]), "r"((b)[0]), "r"((b)[1]))
#define CPASYNC16(dst, src) \
    asm volatile("cp.async.ca.shared.global [%0], [%1], 16;" :: "r"(dst), "l"(src))
#define CPCOMMIT() asm volatile("cp.async.commit_group;")

// ---------------- weight prep: hi/lo bf16, swizzled tile image per tap ----------------
__global__ void prep3_kernel(const float* __restrict__ rw, const float* __restrict__ w3,
                             char* __restrict__ dst)
{
    const int t = blockIdx.x, c = blockIdx.y;
    const float* w = (c < 18) ? (rw + (size_t)c * 36864) : (w3 + (size_t)(c - 18) * 36864);
    const float scale = (c < 18) ? (1.0f / 24.0f) : 1.0f;
    char* d = dst + ((size_t)c * 9 + t) * 16384;
    for (int e = threadIdx.x; e < 4096; e += 256) {
        int oc = e >> 6, ic = e & 63;
        float v = w[(oc * 64 + ic) * 9 + t] * scale;
        __nv_bfloat16 h = __float2bfloat16(v);
        __nv_bfloat16 l = __float2bfloat16(v - __bfloat162float(h));
        uint32_t off = SWZ128((uint32_t)(oc * 128 + ic * 2));
        *(unsigned short*)(d + off)        = __bfloat16_as_ushort(h);
        *(unsigned short*)(d + 8192 + off) = __bfloat16_as_ushort(l);
    }
}
__global__ void prep5_kernel(const float* __restrict__ w5, char* __restrict__ dst)
{
    const int t = blockIdx.x, c = blockIdx.y;
    const float* w = w5 + (size_t)c * 102400;
    char* d = dst + ((size_t)c * 25 + t) * 16384;
    for (int e = threadIdx.x; e < 4096; e += 256) {
        int oc = e >> 6, ic = e & 63;
        float v = w[(oc * 64 + ic) * 25 + t];
        __nv_bfloat16 h = __float2bfloat16(v);
        __nv_bfloat16 l = __float2bfloat16(v - __bfloat162float(h));
        uint32_t off = SWZ128((uint32_t)(oc * 128 + ic * 2));
        *(unsigned short*)(d + off)        = __bfloat16_as_ushort(h);
        *(unsigned short*)(d + 8192 + off) = __bfloat16_as_ushort(l);
    }
}

// ---------------------------------------------------------------------------
// bf16 HMMA conv (KDIM 3 or 5), pad=KDIM/2.  Tile: 16 wide x TH high.
// 512 thr = 16 warps: wm = warp&7 (M), wn = warp>>3 (N: 32 oc each).
// MPW = TH/8 m16-fragments per warp; fragment (wm,mi) covers pixel row
// y = wm*MPW+mi, x = 0..15.
// A: SMEM halo tile, row = pixel (iy*IW+ix), 128B of 64 ic bf16 (swizzled), hi+lo.
// B: per-tap 16KB hi/lo, cp.async TRIPLE buffered, 1 barrier per tap.
// Split: acc += Ahi*Bhi + Ahi*Blo + Alo*Bhi (fp32 accum).
// ---------------------------------------------------------------------------
template<int KDIM, int TH, int MOD, int ACT, int RES>
__global__ void __launch_bounds__(512, 1) convMMA_kernel(
    const float* __restrict__ x, const char* __restrict__ wpack,
    const float* __restrict__ bias, const float* __restrict__ cond,
    const float* __restrict__ res, float* __restrict__ out)
{
    constexpr int TAPS = KDIM * KDIM;
    constexpr int HALO = KDIM / 2;
    constexpr int IW = 16 + 2 * HALO;
    constexpr int IH = TH + 2 * HALO;
    constexpr int NR = IH * IW;
    constexpr int MPW = TH / 8;

    extern __shared__ __align__(16) char sm[];
    char* actH = sm;
    char* actL = sm + NR * 128;
    char* wts  = sm + 2 * NR * 128;   // 3 x 16KB

    const int tid = threadIdx.x, lane = tid & 31, warp = tid >> 5;
    const int wm = warp & 7, wn = warp >> 3;
    const int gx0 = blockIdx.x * 16, gy0 = blockIdx.y * TH, b = blockIdx.z;
    const int cb = b * 64;
    const float* xb = x + (size_t)b * CHW;

    // ---- stage activation halo tile as bf16 hi/lo (swizzled rows) ----
    for (int e = tid; e < 32 * NR; e += 512) {
        int j = e / NR, p = e - j * NR;
        int iy = p / IW, ix = p - iy * IW;
        int gy = gy0 + iy - HALO, gx = gx0 + ix - HALO;
        float v0 = 0.f, v1 = 0.f;
        if ((unsigned)gy < 128u && (unsigned)gx < 128u) {
            const float* q = xb + (size_t)(2 * j) * HW + gy * 128 + gx;
            v0 = q[0]; v1 = q[HW];
            if (MOD) { v0 *= cond[cb + 2 * j]; v1 *= cond[cb + 2 * j + 1]; }
        }
        __nv_bfloat16 h0 = __float2bfloat16(v0), h1 = __float2bfloat16(v1);
        __nv_bfloat16 l0 = __float2bfloat16(v0 - __bfloat162float(h0));
        __nv_bfloat16 l1 = __float2bfloat16(v1 - __bfloat162float(h1));
        uint32_t off = (uint32_t)p * 128 + ((4u * j) ^ ((uint32_t)(p & 7) << 4));
        *(uint32_t*)(actH + off) = ((uint32_t)__bfloat16_as_ushort(h1) << 16) | __bfloat16_as_ushort(h0);
        *(uint32_t*)(actL + off) = ((uint32_t)__bfloat16_as_ushort(l1) << 16) | __bfloat16_as_ushort(l0);
    }

    const uint32_t actHa = smem_u32(actH);
    const uint32_t actLa = smem_u32(actL);
    const uint32_t wtsA  = smem_u32(wts);

    auto prefetch = [&](int tap, int buf) {
        const char* src = wpack + (size_t)tap * 16384;
        uint32_t dst = wtsA + (uint32_t)buf * 16384u;
#pragma unroll
        for (int i = 0; i < 2; i++)
            CPASYNC16(dst + (tid + i * 512) * 16, src + (tid + i * 512) * 16);
        CPCOMMIT();
    };
    prefetch(0, 0);
    if (TAPS > 1) prefetch(1, 1);

    float c[MPW][4][4];
#pragma unroll
    for (int mi = 0; mi < MPW; mi++)
#pragma unroll
        for (int ni = 0; ni < 4; ni++)
#pragma unroll
            for (int k = 0; k < 4; k++) c[mi][ni][k] = 0.f;

    const int asub = lane >> 3;
    const int arow = ((asub & 1) << 3) + (lane & 7);
    const int ack  = asub >> 1;
    const int bmat = lane >> 3;
    const int bocl = ((bmat >> 1) << 3) + (lane & 7);
    const int bck  = bmat & 1;

    for (int t = 0; t < TAPS; ++t) {
        asm volatile("cp.async.wait_group 1;");   // tap t's weights landed
        __syncthreads();                           // data ready + all warps past tap t-1 reads
        if (t + 2 < TAPS) prefetch(t + 2, (t + 2) % 3);

        const int ky = t / KDIM, kx = t - ky * KDIM;
        const uint32_t wb = wtsA + (uint32_t)(t % 3) * 16384u;

#pragma unroll
        for (int ks = 0; ks < 4; ++ks) {
            uint32_t BH[4][2], BL[4][2];
#pragma unroll
            for (int gg = 0; gg < 2; ++gg) {
                int ocr = wn * 32 + gg * 16 + bocl;
                uint32_t off = (uint32_t)ocr * 128 + ((uint32_t)((ks * 2 + bck) ^ (ocr & 7)) << 4);
                uint32_t r[4];
                LDMX4(r, wb + off);
                BH[gg * 2][0] = r[0]; BH[gg * 2][1] = r[1];
                BH[gg * 2 + 1][0] = r[2]; BH[gg * 2 + 1][1] = r[3];
                LDMX4(r, wb + 8192 + off);
                BL[gg * 2][0] = r[0]; BL[gg * 2][1] = r[1];
                BL[gg * 2 + 1][0] = r[2]; BL[gg * 2 + 1][1] = r[3];
            }
#pragma unroll
            for (int mi = 0; mi < MPW; ++mi) {
                uint32_t AH[4], AL[4];
                int rp = (wm * MPW + mi + ky) * IW + arow + kx;
                uint32_t off = (uint32_t)rp * 128 + ((uint32_t)((ks * 2 + ack) ^ (rp & 7)) << 4);
                LDMX4(AH, actHa + off);
                LDMX4(AL, actLa + off);
#pragma unroll
                for (int ni = 0; ni < 4; ++ni) {
                    MMA16816(c[mi][ni], AH, BH[ni]);
                    MMA16816(c[mi][ni], AH, BL[ni]);
                    MMA16816(c[mi][ni], AL, BH[ni]);
                }
            }
        }
    }

    // ---- epilogue ----
    const int r0 = lane >> 2, q2 = (lane & 3) * 2;
#pragma unroll
    for (int mi = 0; mi < MPW; ++mi) {
        const int y = wm * MPW + mi;
#pragma unroll
        for (int half = 0; half < 2; ++half) {
            const int xcol = r0 + half * 8;
            const int sp = (gy0 + y) * 128 + gx0 + xcol;
#pragma unroll
            for (int ni = 0; ni < 4; ++ni) {
#pragma unroll
                for (int dq = 0; dq < 2; ++dq) {
                    const int n = wn * 32 + ni * 8 + q2 + dq;
                    float v = c[mi][ni][half * 2 + dq];
                    v += MOD ? __ldg(&bias[(cb + n) >> 2]) : __ldg(&bias[n]);
                    if (ACT == 1) v = fmaxf(v, 0.f);
                    if (ACT == 2) v = v > 0.f ? v : 0.01f * v;
                    if (RES) v += __ldg(&res[(size_t)(cb + n) * HW + sp]);
                    out[(size_t)(cb + n) * HW + sp] = v;
                }
            }
        }
    }
}

// ---------------- fp32 1x1 conv ----------------
template<int ACT>
__global__ void __launch_bounds__(256) conv1_kernel(
    const float* __restrict__ x, const float* __restrict__ w,
    const float* __restrict__ bias, float* __restrict__ out)
{
    __shared__ float xs[64][64];
    __shared__ __align__(16) float ws[64][68];
    const int tid = threadIdx.x;
    const int b  = blockIdx.y;
    const int p0 = blockIdx.x * 64;
    for (int e = tid; e < 4096; e += 256) {
        int ic = e >> 6, px = e & 63;
        xs[ic][px] = x[(size_t)b * CHW + ic * HW + p0 + px];
    }
    for (int e = tid; e < 4096; e += 256) {
        int ocw = e >> 6, ic = e & 63;
        ws[ic][ocw] = w[ocw * 64 + ic];
    }
    __syncthreads();
    const int px = tid & 63;
    const int oc0 = (tid >> 6) * 16;
    float acc[16];
#pragma unroll
    for (int o = 0; o < 16; o++) acc[o] = 0.f;
#pragma unroll 4
    for (int ic = 0; ic < 64; ic++) {
        float xv = xs[ic][px];
        const float4* wr = (const float4*)&ws[ic][oc0];
        float4 w0 = wr[0], w1 = wr[1], w2 = wr[2], w3 = wr[3];
        acc[0]+=xv*w0.x; acc[1]+=xv*w0.y; acc[2]+=xv*w0.z; acc[3]+=xv*w0.w;
        acc[4]+=xv*w1.x; acc[5]+=xv*w1.y; acc[6]+=xv*w1.z; acc[7]+=xv*w1.w;
        acc[8]+=xv*w2.x; acc[9]+=xv*w2.y; acc[10]+=xv*w2.z; acc[11]+=xv*w2.w;
        acc[12]+=xv*w3.x; acc[13]+=xv*w3.y; acc[14]+=xv*w3.z; acc[15]+=xv*w3.w;
    }
#pragma unroll
    for (int o = 0; o < 16; o++) {
        float v = acc[o] + bias[oc0 + o];
        if (ACT == 2) v = v > 0.f ? v : 0.01f * v;
        out[(size_t)b * CHW + (oc0 + o) * HW + p0 + px] = v;
    }
}

// ---------------- small kernels ----------------
__global__ void pool_kernel(const float* __restrict__ x, float* __restrict__ mx, float* __restrict__ av)
{
    const int bc = blockIdx.x;
    const float* p = x + (size_t)bc * HW;
    float m = -3.402823466e38f, s = 0.f;
    for (int i = threadIdx.x; i < HW; i += 256) { float v = p[i]; m = fmaxf(m, v); s += v; }
#pragma unroll
    for (int o = 16; o; o >>= 1) {
        m = fmaxf(m, __shfl_xor_sync(0xFFFFFFFFu, m, o));
        s += __shfl_xor_sync(0xFFFFFFFFu, s, o);
    }
    __shared__ float sm_[8], ss_[8];
    int wid = threadIdx.x >> 5;
    if ((threadIdx.x & 31) == 0) { sm_[wid] = m; ss_[wid] = s; }
    __syncthreads();
    if (threadIdx.x == 0) {
        float mm = sm_[0], st = ss_[0];
        for (int i = 1; i < 8; i++) { mm = fmaxf(mm, sm_[i]); st += ss_[i]; }
        mx[bc] = mm; av[bc] = st * (1.0f / 16384.0f);
    }
}
__global__ void coef_kernel(const float* __restrict__ mx, const float* __restrict__ av,
                            const float* __restrict__ cw1, const float* __restrict__ cw2,
                            const float* __restrict__ fw, const float* __restrict__ fb,
                            float* __restrict__ coef)
{
    __shared__ float hm[16], ha[16];
    int t = threadIdx.x;
    if (t < 32) {
        int which = t >> 4, t2 = t & 15, b = t2 >> 2, j = t2 & 3;
        const float* v = which ? av : mx;
        float s = 0.f;
        for (int c = 0; c < 64; c++) s += v[b * 64 + c] * cw1[j * 64 + c];
        s = fmaxf(s, 0.f);
        if (which) ha[t2] = s; else hm[t2] = s;
    }
    __syncthreads();
    int b = t >> 6, c = t & 63;
    float se_m = 0.f, se_a = 0.f;
#pragma unroll
    for (int j = 0; j < 4; j++) {
        se_m += hm[b * 4 + j] * cw2[c * 4 + j];
        se_a += ha[b * 4 + j] * cw2[c * 4 + j];
    }
    float xll = 1.f / (1.f + expf(-(se_m + se_a)));
    coef[t] = fw[1] * (fw[0] * xll + fb[0]) + fb[1];
}
__global__ void combine_kernel(const float* __restrict__ s1, const float* __restrict__ s3,
                               const float* __restrict__ s5, const float* __restrict__ coef,
                               float* __restrict__ out)
{
    int fi = (blockIdx.x * 256 + threadIdx.x) * 4;
    float cf = coef[fi >> 14];
    float4 a = *(const float4*)(s1 + fi);
    float4 b = *(const float4*)(s3 + fi);
    float4 c = *(const float4*)(s5 + fi);
    float4 r;
    r.x = cf * (a.x + b.x + c.x); r.y = cf * (a.y + b.y + c.y);
    r.z = cf * (a.z + b.z + c.z); r.w = cf * (a.w + b.w + c.w);
    *(float4*)(out + fi) = r;
}
__global__ void add_kernel(float* __restrict__ a, const float* __restrict__ b)
{
    int fi = (blockIdx.x * 256 + threadIdx.x) * 4;
    float4 u = *(float4*)(a + fi);
    float4 v = *(const float4*)(b + fi);
    u.x += v.x; u.y += v.y; u.z += v.z; u.w += v.w;
    *(float4*)(a + fi) = u;
}
__global__ void mapmul_kernel(float* __restrict__ a, const float* __restrict__ mp)
{
    int fi = (blockIdx.x * 256 + threadIdx.x) * 4;
    int b = fi >> 20, s = fi & (HW - 1);
    float4 m = *(const float4*)(mp + b * HW + s);
    float4 v = *(float4*)(a + fi);
    v.x *= (1.f + m.x); v.y *= (1.f + m.y); v.z *= (1.f + m.z); v.w *= (1.f + m.w);
    *(float4*)(a + fi) = v;
}

// ---------------- launch ----------------
template<int KDIM, int TH, int MOD, int ACT, int RES>
static void launch_conv(const float* x, const char* wp, const float* bias,
                        const float* cond, const float* res, float* out)
{
    constexpr int HALO = KDIM / 2;
    constexpr int NR = (TH + 2 * HALO) * (16 + 2 * HALO);
    constexpr int SMEMB = 2 * NR * 128 + 3 * 16384;
    cudaFuncSetAttribute(convMMA_kernel<KDIM, TH, MOD, ACT, RES>,
                         cudaFuncAttributeMaxDynamicSharedMemorySize, SMEMB);
    convMMA_kernel<KDIM, TH, MOD, ACT, RES><<<dim3(8, 128 / TH, 4), 512, SMEMB>>>(x, wp, bias, cond, res, out);
}

extern "C" void kernel_launch(void* const* d_in, const int* in_sizes, int n_in,
                              void* d_out, int out_size)
{
    (void)in_sizes; (void)n_in; (void)out_size;
    const float* x   = (const float*)d_in[0];
    const float* c1  = (const float*)d_in[1];
    const float* c2  = (const float*)d_in[2];
    const float* mp  = (const float*)d_in[3];
    const float* rw  = (const float*)d_in[4];
    const float* rb  = (const float*)d_in[5];
    const float* w1  = (const float*)d_in[6];
    const float* b1  = (const float*)d_in[7];
    const float* w3  = (const float*)d_in[8];
    const float* b3  = (const float*)d_in[9];
    const float* w5  = (const float*)d_in[10];
    const float* b5  = (const float*)d_in[11];
    const float* cw1 = (const float*)d_in[12];
    const float* cw2 = (const float*)d_in[13];
    const float* fw  = (const float*)d_in[14];
    const float* fb  = (const float*)d_in[15];
    float* OUT = (float*)d_out;

    float* base;  cudaGetSymbolAddress((void**)&base, g_buf);
    char* W3P;    cudaGetSymbolAddress((void**)&W3P, g_w3pack);
    char* W5P;    cudaGetSymbolAddress((void**)&W5P, g_w5pack);
    float *MX, *AV, *CF;
    cudaGetSymbolAddress((void**)&MX, g_mx);
    cudaGetSymbolAddress((void**)&AV, g_av);
    cudaGetSymbolAddress((void**)&CF, g_cf);

    float* CUR = base;
    float* TMP = base + (size_t)NTOT;
    float* S1  = base + 2 * (size_t)NTOT;
    float* S3  = base + 3 * (size_t)NTOT;
    float* S5  = base + 4 * (size_t)NTOT;
    float* E1  = base + 5 * (size_t)NTOT;
    float* E2  = base + 6 * (size_t)NTOT;
    float* E3  = base + 7 * (size_t)NTOT;
    float* E4  = base + 8 * (size_t)NTOT;

    prep3_kernel<<<dim3(9, 28), 256>>>(rw, w3, W3P);
    prep5_kernel<<<dim3(25, 10), 256>>>(w5, W5P);

    const dim3 G1(256, 4);
    const int EG = NTOT / 4 / 256;

    auto resb = [&](const float* in, float* out, int i, const float* cond) {
        const char* wp = W3P + (size_t)(i * 2) * 9 * 16384;
        const float* bi = rb + (size_t)i * 2 * 64;
        launch_conv<3, 32, 1, 1, 0>(in, wp, bi, cond, nullptr, TMP);
        launch_conv<3, 32, 1, 0, 1>(TMP, wp + 9 * 16384, bi + 64, cond + 256, in, out);
    };
    auto mfe = [&](int i) {
        pool_kernel<<<256, 256>>>(CUR, MX, AV);
        coef_kernel<<<1, 256>>>(MX, AV, cw1 + i * 256, cw2 + i * 256, fw + i * 2, fb + i * 2, CF);
        const float* w1i = w1 + (size_t)i * 2 * 64 * 64;
        const char* w3p = W3P + (size_t)(18 + i * 2) * 9 * 16384;
        const char* w5p = W5P + (size_t)(i * 2) * 25 * 16384;
        conv1_kernel<2><<<G1, 256>>>(CUR, w1i, b1 + i * 128, TMP);
        conv1_kernel<0><<<G1, 256>>>(TMP, w1i + 64 * 64, b1 + i * 128 + 64, S1);
        launch_conv<3, 32, 0, 2, 0>(CUR, w3p, b3 + i * 128, nullptr, nullptr, TMP);
        launch_conv<3, 32, 0, 0, 0>(TMP, w3p + 9 * 16384, b3 + i * 128 + 64, nullptr, nullptr, S3);
        launch_conv<5, 16, 0, 2, 0>(CUR, w5p, b5 + i * 128, nullptr, nullptr, TMP);
        launch_conv<5, 16, 0, 0, 0>(TMP, w5p + 25 * 16384, b5 + i * 128 + 64, nullptr, nullptr, S5);
        combine_kernel<<<EG, 256>>>(S1, S3, S5, CF, CUR);
    };

    const size_t NB = (size_t)NTOT * sizeof(float);

    resb(x, CUR, 0, c1); mfe(0); resb(CUR, CUR, 0, c1);
    cudaMemcpyAsync(E1, CUR, NB, cudaMemcpyDeviceToDevice);

    for (int k = 0; k < 3; k++) resb(CUR, CUR, 1, c1 + 512);
    cudaMemcpyAsync(E2, CUR, NB, cudaMemcpyDeviceToDevice);

    resb(CUR, CUR, 2, c1 + 1024); mfe(1); resb(CUR, CUR, 2, c1 + 1024);
    cudaMemcpyAsync(E3, CUR, NB, cudaMemcpyDeviceToDevice);

    for (int k = 0; k < 3; k++) resb(CUR, CUR, 3, c1 + 1536);
    cudaMemcpyAsync(E4, CUR, NB, cudaMemcpyDeviceToDevice);

    resb(CUR, CUR, 4, c2); mfe(2);
    mapmul_kernel<<<EG, 256>>>(CUR, mp);
    resb(CUR, CUR, 4, c2);
    add_kernel<<<EG, 256>>>(CUR, E4);

    for (int k = 0; k < 3; k++) resb(CUR, CUR, 5, c1 + 5 * 512);

    add_kernel<<<EG, 256>>>(CUR, E3);
    resb(CUR, CUR, 6, c1 + 6 * 512); mfe(3); resb(CUR, CUR, 6, c1 + 6 * 512);

    add_kernel<<<EG, 256>>>(CUR, E2);
    for (int k = 0; k < 3; k++) resb(CUR, CUR, 7, c1 + 7 * 512);

    add_kernel<<<EG, 256>>>(CUR, E1);
    resb(CUR, CUR, 8, c1 + 8 * 512);
    mfe(4);
    {
        const char* wp = W3P + (size_t)(8 * 2) * 9 * 16384;
        const float* bi = rb + (size_t)8 * 2 * 64;
        const float* cond = c1 + 8 * 512;
        launch_conv<3, 32, 1, 1, 0>(CUR, wp, bi, cond, nullptr, TMP);
        launch_conv<3, 32, 1, 0, 1>(TMP, wp + 9 * 16384, bi + 64, cond + 256, CUR, OUT);
    }
}